// round 4
// baseline (speedup 1.0000x reference)
#include <cuda_runtime.h>
#include <cstdint>
#include <cstddef>

// Problem constants
#define NODES   49152
#define FDIM    128
#define DTOT    9
#define NB      12      // nodes per CTA (49152 = 4096 * 12)
#define THREADS 256
#define NPT     6       // nodes per thread-group half (two groups of 128 threads)

// smem float offsets
//  T_s : [NB][128][12]          = 18432 floats
//  WB0 : [128][129]             = 16512 floats
//  WB1 : [128][129]             = 16512 floats   (WB0..WB1 reused as ls_w [128][257] = 32896 <= 33024)
//  SB  : [NB][128]              =  1536 floats
//  PB  : [NB][256]              =  3072 floats
//  SS  : [NB][128]              =  1536 floats
// total = 57600 floats = 230400 bytes

static __device__ __forceinline__ void stage_w129(float* dst, const float* __restrict__ g, int tid) {
    const float4* g4 = reinterpret_cast<const float4*>(g);
    #pragma unroll 4
    for (int i = tid; i < 4096; i += THREADS) {     // 128x128 / 4
        float4 w = g4[i];
        int v  = i >> 5;            // row (output channel)
        int u0 = (i & 31) << 2;     // starting input channel
        dst[(u0 + 0) * 129 + v] = w.x;
        dst[(u0 + 1) * 129 + v] = w.y;
        dst[(u0 + 2) * 129 + v] = w.z;
        dst[(u0 + 3) * 129 + v] = w.w;
    }
}

// q/k accumulation for one irrep block: s_reg[j] += cf * sum_d q[d]*k[d]
template<int OFF, int DD>
static __device__ __forceinline__ void qk_pass(const float* __restrict__ T_s,
                                               const float* __restrict__ W0,
                                               const float* __restrict__ W1,
                                               int v, int nbase, float cf,
                                               float s_reg[NPT]) {
    float aq[NPT][DD];
    float ak[NPT][DD];
    #pragma unroll
    for (int j = 0; j < NPT; j++)
        #pragma unroll
        for (int dd = 0; dd < DD; dd++) { aq[j][dd] = 0.f; ak[j][dd] = 0.f; }

    #pragma unroll 2
    for (int u = 0; u < 128; u++) {
        float wq = W0[u * 129 + v];
        float wk = W1[u * 129 + v];
        #pragma unroll
        for (int j = 0; j < NPT; j++) {
            const float* tp = T_s + ((nbase + j) * 128 + u) * 12;
            float tv[DD];
            if constexpr (DD == 1) {
                tv[0] = tp[0];
            } else if constexpr (DD == 3) {
                tv[0] = tp[1];
                float2 t2 = *reinterpret_cast<const float2*>(tp + 2);
                tv[1] = t2.x; tv[2] = t2.y;
            } else {
                float4 t4 = *reinterpret_cast<const float4*>(tp + 4);
                tv[0] = t4.x; tv[1] = t4.y; tv[2] = t4.z; tv[3] = t4.w;
                tv[4] = tp[8];
            }
            #pragma unroll
            for (int dd = 0; dd < DD; dd++) {
                aq[j][dd] = fmaf(wq, tv[dd], aq[j][dd]);
                ak[j][dd] = fmaf(wk, tv[dd], ak[j][dd]);
            }
        }
    }
    #pragma unroll
    for (int j = 0; j < NPT; j++) {
        float p = 0.f;
        #pragma unroll
        for (int dd = 0; dd < DD; dd++) p = fmaf(aq[j][dd], ak[j][dd], p);
        s_reg[j] += cf * p;
    }
}

// v accumulation + scaled store for one irrep block:
// tu[n,v,OFF+dd] = sd[n,v] * w2[l,v] * INV_SQRT_F * sum_u Wv[v,u] T[n,u,OFF+dd]
template<int OFF, int DD>
static __device__ __forceinline__ void v_pass(const float* __restrict__ T_s,
                                              const float* __restrict__ W0,
                                              const float* __restrict__ PB,
                                              const float* __restrict__ w2l,
                                              int v, int nbase, int node0,
                                              float* __restrict__ outT) {
    float av[NPT][DD];
    #pragma unroll
    for (int j = 0; j < NPT; j++)
        #pragma unroll
        for (int dd = 0; dd < DD; dd++) av[j][dd] = 0.f;

    #pragma unroll 2
    for (int u = 0; u < 128; u++) {
        float wv = W0[u * 129 + v];
        #pragma unroll
        for (int j = 0; j < NPT; j++) {
            const float* tp = T_s + ((nbase + j) * 128 + u) * 12;
            float tv[DD];
            if constexpr (DD == 1) {
                tv[0] = tp[0];
            } else if constexpr (DD == 3) {
                tv[0] = tp[1];
                float2 t2 = *reinterpret_cast<const float2*>(tp + 2);
                tv[1] = t2.x; tv[2] = t2.y;
            } else {
                float4 t4 = *reinterpret_cast<const float4*>(tp + 4);
                tv[0] = t4.x; tv[1] = t4.y; tv[2] = t4.z; tv[3] = t4.w;
                tv[4] = tp[8];
            }
            #pragma unroll
            for (int dd = 0; dd < DD; dd++)
                av[j][dd] = fmaf(wv, tv[dd], av[j][dd]);
        }
    }
    const float INV_SQRT_F = 0.08838834764831845f;   // 1/sqrt(128)
    float w2v = w2l[v];
    #pragma unroll
    for (int j = 0; j < NPT; j++) {
        int n = nbase + j;
        float scale = PB[n * 256 + 128 + v] * w2v * INV_SQRT_F;
        size_t base = (size_t)(node0 + n) * (FDIM * DTOT) + (size_t)v * DTOT + OFF;
        #pragma unroll
        for (int dd = 0; dd < DD; dd++)
            outT[base + dd] = scale * av[j][dd];
    }
}

__global__ void __launch_bounds__(THREADS, 1)
tp_attn_kernel(const float* __restrict__ Tg, const float* __restrict__ Sg,
               const float* __restrict__ Wq, const float* __restrict__ Wk,
               const float* __restrict__ Wv, const float* __restrict__ w2,
               const float* __restrict__ lsw, const float* __restrict__ lsb,
               const float* __restrict__ lvw, const float* __restrict__ lvb,
               float* __restrict__ outT, float* __restrict__ out2) {
    extern __shared__ float smem[];
    float* T_s = smem;
    float* WB0 = smem + 18432;
    float* WB1 = WB0 + 16512;
    float* SB  = WB1 + 16512;
    float* PB  = SB + 1536;
    float* SS  = PB + 3072;

    const int tid   = threadIdx.x;
    const int lane  = tid & 31;
    const int wid   = tid >> 5;
    const int v     = tid & 127;
    const int nbase = (tid >> 7) * NPT;
    const int node0 = blockIdx.x * NB;

    // ---- stage T tile: global [n][u][9] -> smem [n][u][12] (padded, 16B-aligned rows)
    {
        const float4* g4 = reinterpret_cast<const float4*>(Tg + (size_t)node0 * (FDIM * DTOT));
        #pragma unroll 2
        for (int i = tid; i < (NB * FDIM * DTOT) / 4; i += THREADS) {
            float4 t = g4[i];
            float a[4] = { t.x, t.y, t.z, t.w };
            int e = i << 2;
            #pragma unroll
            for (int z = 0; z < 4; z++) {
                int ee = e + z;
                int n = ee / 1152;
                int r = ee - n * 1152;
                int u = r / 9;
                int d = r - u * 9;
                T_s[(n * 128 + u) * 12 + d] = a[z];
            }
        }
    }

    float s_reg[NPT] = { 0.f, 0.f, 0.f, 0.f, 0.f, 0.f };

    // ---- pass A: s[n,v] = sum_l C1_l/F * sum_d q_raw*k_raw
    __syncthreads();
    stage_w129(WB0, Wq,          tid);  stage_w129(WB1, Wk,          tid);
    __syncthreads();
    qk_pass<0, 1>(T_s, WB0, WB1, v, nbase, 0.0045105489780439515f, s_reg); // (1/sqrt3)/128
    __syncthreads();
    stage_w129(WB0, Wq + 16384,  tid);  stage_w129(WB1, Wk + 16384,  tid);
    __syncthreads();
    qk_pass<1, 3>(T_s, WB0, WB1, v, nbase, 0.0026041666666666665f, s_reg); // (1/3)/128
    __syncthreads();
    stage_w129(WB0, Wq + 32768,  tid);  stage_w129(WB1, Wk + 32768,  tid);
    __syncthreads();
    qk_pass<4, 5>(T_s, WB0, WB1, v, nbase, 0.0020171788261496963f, s_reg); // (1/sqrt15)/128

    #pragma unroll
    for (int j = 0; j < NPT; j++) SB[(nbase + j) * 128 + v] = s_reg[j];
    __syncthreads();

    // ---- stage ls_w transposed [u][j], pitch 257 (fits in WB0+WB1 region)
    {
        const float4* g4 = reinterpret_cast<const float4*>(lsw);
        #pragma unroll 4
        for (int i = tid; i < 8192; i += THREADS) {  // 256x128 / 4
            float4 w = g4[i];
            int jrow = i >> 5;
            int u0   = (i & 31) << 2;
            WB0[(u0 + 0) * 257 + jrow] = w.x;
            WB0[(u0 + 1) * 257 + jrow] = w.y;
            WB0[(u0 + 2) * 257 + jrow] = w.z;
            WB0[(u0 + 3) * 257 + jrow] = w.w;
        }
    }
    __syncthreads();

    // ---- pass B: logits + softmax. One warp per node; lane owns 8 of 256 logits.
    for (int n = wid; n < NB; n += 8) {
        float acc[8] = { 0.f, 0.f, 0.f, 0.f, 0.f, 0.f, 0.f, 0.f };
        const float* srow = SB + n * 128;
        #pragma unroll 2
        for (int u = 0; u < 128; u++) {
            float sv = srow[u];
            const float* lrow = WB0 + u * 257 + lane;
            #pragma unroll
            for (int kk = 0; kk < 8; kk++)
                acc[kk] = fmaf(sv, lrow[kk << 5], acc[kk]);
        }
        #pragma unroll
        for (int kk = 0; kk < 8; kk++) acc[kk] += lsb[(kk << 5) + lane];
        float m = acc[0];
        #pragma unroll
        for (int kk = 1; kk < 8; kk++) m = fmaxf(m, acc[kk]);
        #pragma unroll
        for (int off = 16; off > 0; off >>= 1)
            m = fmaxf(m, __shfl_xor_sync(0xffffffffu, m, off));
        float ssum = 0.f;
        #pragma unroll
        for (int kk = 0; kk < 8; kk++) { acc[kk] = __expf(acc[kk] - m); ssum += acc[kk]; }
        #pragma unroll
        for (int off = 16; off > 0; off >>= 1)
            ssum += __shfl_xor_sync(0xffffffffu, ssum, off);
        float inv = 1.f / ssum;
        #pragma unroll
        for (int kk = 0; kk < 8; kk++)
            PB[n * 256 + (kk << 5) + lane] = acc[kk] * inv;
    }
    __syncthreads();

    // ---- out2: su * silu(S @ lvs_w^T + b)
    stage_w129(WB0, lvw, tid);
    {
        const float4* g4 = reinterpret_cast<const float4*>(Sg + (size_t)node0 * FDIM);
        #pragma unroll 2
        for (int i = tid; i < (NB * FDIM) / 4; i += THREADS)
            reinterpret_cast<float4*>(SS)[i] = g4[i];
    }
    __syncthreads();
    {
        float acc[NPT] = { 0.f, 0.f, 0.f, 0.f, 0.f, 0.f };
        #pragma unroll 2
        for (int c = 0; c < 128; c++) {
            float w = WB0[c * 129 + v];
            #pragma unroll
            for (int j = 0; j < NPT; j++)
                acc[j] = fmaf(SS[(nbase + j) * 128 + c], w, acc[j]);
        }
        float b = lvb[v];
        #pragma unroll
        for (int j = 0; j < NPT; j++) {
            int n = nbase + j;
            float z   = acc[j] + b;
            float sig = 1.f / (1.f + __expf(-z));
            out2[(size_t)(node0 + n) * FDIM + v] = PB[n * 256 + v] * (z * sig);
        }
    }

    // ---- pass C: tu = sd * (Wv T) * INV_SQRT_F * w2
    __syncthreads();
    stage_w129(WB0, Wv, tid);
    __syncthreads();
    v_pass<0, 1>(T_s, WB0, PB, w2,       v, nbase, node0, outT);
    __syncthreads();
    stage_w129(WB0, Wv + 16384, tid);
    __syncthreads();
    v_pass<1, 3>(T_s, WB0, PB, w2 + 128, v, nbase, node0, outT);
    __syncthreads();
    stage_w129(WB0, Wv + 32768, tid);
    __syncthreads();
    v_pass<4, 5>(T_s, WB0, PB, w2 + 256, v, nbase, node0, outT);
}

extern "C" void kernel_launch(void* const* d_in, const int* in_sizes, int n_in,
                              void* d_out, int out_size) {
    const float* Tg  = (const float*)d_in[0];
    const float* Sg  = (const float*)d_in[1];
    const float* Wq  = (const float*)d_in[2];
    const float* Wk  = (const float*)d_in[3];
    const float* Wv  = (const float*)d_in[4];
    const float* w2  = (const float*)d_in[5];
    const float* lsw = (const float*)d_in[6];
    const float* lsb = (const float*)d_in[7];
    const float* lvw = (const float*)d_in[8];
    const float* lvb = (const float*)d_in[9];

    float* out  = (float*)d_out;
    float* outT = out;                                         // tu: N*F*D floats
    float* out2 = out + (size_t)NODES * FDIM * DTOT;           // out2: N*F floats

    const int smem_bytes = 230400;
    cudaFuncSetAttribute(tp_attn_kernel,
                         cudaFuncAttributeMaxDynamicSharedMemorySize, smem_bytes);
    tp_attn_kernel<<<NODES / NB, THREADS, smem_bytes>>>(
        Tg, Sg, Wq, Wk, Wv, w2, lsw, lsb, lvw, lvb, outT, out2);
}

// round 5
// speedup vs baseline: 1.2280x; 1.2280x over previous
#include <cuda_runtime.h>
#include <cstdint>
#include <cstddef>

// Problem constants
#define NODES   49152
#define FDIM    128
#define DTOT    9
#define NB      12      // nodes per CTA
#define THREADS 384     // 3 groups x 128 threads; each group handles 4 nodes
#define NGRP    4       // nodes per group (2 packed pairs)

typedef unsigned long long ull;

// packed f32x2 helpers (sm_103a)
#define FMA2(d_, a_, b_, c_) \
    asm("fma.rn.f32x2 %0, %1, %2, %3;" : "=l"(d_) : "l"(a_), "l"(b_), "l"(c_))
#define PACKDUP(d_, f_) \
    asm("mov.b64 %0, {%1, %1};" : "=l"(d_) : "r"(__float_as_uint(f_)))
#define UNPACK2(lo_, hi_, x_) \
    asm("mov.b64 {%0, %1}, %2;" : "=r"(lo_), "=r"(hi_) : "l"(x_))

// smem float offsets
//  T_s : [128 u][12 d][12 n]   = 18432
//  WB0 : [128][129]            = 16512
//  WB1 : [128][129]            = 16512  (WB0..WB1 also holds ls_w [128][257]=32896; WB1 doubles as TU staging)
//  SB  : [12][128]             =  1536
//  PB  : [12][256]             =  3072
//  SS2 : [128 c][12 n]         =  1536
// total 57600 floats = 230400 bytes
#define OFF_T    0
#define OFF_WB0  18432
#define OFF_WB1  34944
#define OFF_SB   51456
#define OFF_PB   52992
#define OFF_SS2  56064

static __device__ __forceinline__ void stage_w129(float* dst, const float* __restrict__ g, int tid) {
    const float4* g4 = reinterpret_cast<const float4*>(g);
    #pragma unroll 4
    for (int i = tid; i < 4096; i += THREADS) {     // 128x128 / 4
        float4 w = g4[i];
        int v  = i >> 5;            // output channel (row of W)
        int u0 = (i & 31) << 2;     // input channel
        dst[(u0 + 0) * 129 + v] = w.x;
        dst[(u0 + 1) * 129 + v] = w.y;
        dst[(u0 + 2) * 129 + v] = w.z;
        dst[(u0 + 3) * 129 + v] = w.w;
    }
}

// q,k accumulation for one irrep block (packed over node pairs)
template<int OFF, int DD>
static __device__ __forceinline__ void qk_pass(const float* __restrict__ T_s,
                                               const float* __restrict__ W0,
                                               const float* __restrict__ W1,
                                               int v, int ng, float cf,
                                               float s_reg[NGRP]) {
    ull aq[2][DD], ak[2][DD];
    #pragma unroll
    for (int p = 0; p < 2; p++)
        #pragma unroll
        for (int d = 0; d < DD; d++) { aq[p][d] = 0ull; ak[p][d] = 0ull; }

    #pragma unroll 2
    for (int u = 0; u < 128; u++) {
        float wq = W0[u * 129 + v];
        float wk = W1[u * 129 + v];
        ull wq2, wk2;
        PACKDUP(wq2, wq);
        PACKDUP(wk2, wk);
        #pragma unroll
        for (int d = 0; d < DD; d++) {
            ulonglong2 t = *reinterpret_cast<const ulonglong2*>(
                T_s + (u * 12 + OFF + d) * 12 + ng);
            FMA2(aq[0][d], wq2, t.x, aq[0][d]);
            FMA2(aq[1][d], wq2, t.y, aq[1][d]);
            FMA2(ak[0][d], wk2, t.x, ak[0][d]);
            FMA2(ak[1][d], wk2, t.y, ak[1][d]);
        }
    }
    #pragma unroll
    for (int p = 0; p < 2; p++) {
        ull acc = 0ull;
        #pragma unroll
        for (int d = 0; d < DD; d++) FMA2(acc, aq[p][d], ak[p][d], acc);
        unsigned lo, hi;
        UNPACK2(lo, hi, acc);
        s_reg[2 * p + 0] += cf * __uint_as_float(lo);
        s_reg[2 * p + 1] += cf * __uint_as_float(hi);
    }
}

// v accumulation for one irrep block; scaled store into smem TU staging
template<int OFF, int DD>
static __device__ __forceinline__ void v_pass(const float* __restrict__ T_s,
                                              const float* __restrict__ W0,
                                              const float* __restrict__ PB,
                                              const float* __restrict__ w2l,
                                              float* __restrict__ TU_s,
                                              int v, int ng) {
    ull av[2][DD];
    #pragma unroll
    for (int p = 0; p < 2; p++)
        #pragma unroll
        for (int d = 0; d < DD; d++) av[p][d] = 0ull;

    #pragma unroll 2
    for (int u = 0; u < 128; u++) {
        float wv = W0[u * 129 + v];
        ull wv2;
        PACKDUP(wv2, wv);
        #pragma unroll
        for (int d = 0; d < DD; d++) {
            ulonglong2 t = *reinterpret_cast<const ulonglong2*>(
                T_s + (u * 12 + OFF + d) * 12 + ng);
            FMA2(av[0][d], wv2, t.x, av[0][d]);
            FMA2(av[1][d], wv2, t.y, av[1][d]);
        }
    }
    const float INV_SQRT_F = 0.08838834764831845f;   // 1/sqrt(128)
    float w2v = w2l[v] * INV_SQRT_F;
    #pragma unroll
    for (int p = 0; p < 2; p++) {
        int n0 = ng + 2 * p;
        float sc0 = PB[(n0 + 0) * 256 + 128 + v] * w2v;
        float sc1 = PB[(n0 + 1) * 256 + 128 + v] * w2v;
        #pragma unroll
        for (int d = 0; d < DD; d++) {
            unsigned lo, hi;
            UNPACK2(lo, hi, av[p][d]);
            TU_s[(n0 + 0) * 1152 + v * 9 + OFF + d] = sc0 * __uint_as_float(lo);
            TU_s[(n0 + 1) * 1152 + v * 9 + OFF + d] = sc1 * __uint_as_float(hi);
        }
    }
}

__global__ void __launch_bounds__(THREADS, 1)
tp_attn_kernel(const float* __restrict__ Tg, const float* __restrict__ Sg,
               const float* __restrict__ Wq, const float* __restrict__ Wk,
               const float* __restrict__ Wv, const float* __restrict__ w2,
               const float* __restrict__ lsw, const float* __restrict__ lsb,
               const float* __restrict__ lvw, const float* __restrict__ lvb,
               float* __restrict__ outT, float* __restrict__ out2) {
    extern __shared__ float smem[];
    float* T_s  = smem + OFF_T;
    float* WB0  = smem + OFF_WB0;
    float* WB1  = smem + OFF_WB1;
    float* SB   = smem + OFF_SB;
    float* PB   = smem + OFF_PB;
    float* SS2  = smem + OFF_SS2;
    float* TU_s = WB1;                      // reused during v passes

    const int tid   = threadIdx.x;
    const int lane  = tid & 31;
    const int wid   = tid >> 5;
    const int v     = tid & 127;
    const int ng    = (tid >> 7) * NGRP;    // node base for this group (0,4,8)
    const int node0 = blockIdx.x * NB;

    // ---- stage T tile: global [n][u][9] -> smem [u][d][n] (n fastest, NB=12)
    {
        const float4* g4 = reinterpret_cast<const float4*>(Tg + (size_t)node0 * (FDIM * DTOT));
        #pragma unroll
        for (int it = 0; it < 9; it++) {            // 3456 float4 / 384 threads
            int i = it * THREADS + tid;
            float4 t = g4[i];
            float a[4] = { t.x, t.y, t.z, t.w };
            int e = i << 2;
            #pragma unroll
            for (int z = 0; z < 4; z++) {
                int ee = e + z;
                int n = ee / 1152;
                int r = ee - n * 1152;
                int u = r / 9;
                int d = r - u * 9;
                T_s[(u * 12 + d) * 12 + n] = a[z];
            }
        }
    }

    float s_reg[NGRP] = { 0.f, 0.f, 0.f, 0.f };

    // ---- pass A: s[n,v] = sum_l (C1_l/128) * sum_d q_raw*k_raw
    stage_w129(WB0, Wq, tid);  stage_w129(WB1, Wk, tid);
    __syncthreads();
    qk_pass<0, 1>(T_s, WB0, WB1, v, ng, 0.0045105489780439515f, s_reg); // (1/sqrt3)/128
    __syncthreads();
    stage_w129(WB0, Wq + 16384, tid);  stage_w129(WB1, Wk + 16384, tid);
    __syncthreads();
    qk_pass<1, 3>(T_s, WB0, WB1, v, ng, 0.0026041666666666665f, s_reg); // (1/3)/128
    __syncthreads();
    stage_w129(WB0, Wq + 32768, tid);  stage_w129(WB1, Wk + 32768, tid);
    __syncthreads();
    qk_pass<4, 5>(T_s, WB0, WB1, v, ng, 0.0020171788261496963f, s_reg); // (1/sqrt15)/128

    #pragma unroll
    for (int j = 0; j < NGRP; j++) SB[(ng + j) * 128 + v] = s_reg[j];
    __syncthreads();

    // ---- stage ls_w transposed [u][j], pitch 257 (covers WB0+WB1 region)
    {
        const float4* g4 = reinterpret_cast<const float4*>(lsw);
        #pragma unroll 4
        for (int i = tid; i < 8192; i += THREADS) {  // 256x128 / 4
            float4 w = g4[i];
            int jrow = i >> 5;
            int u0   = (i & 31) << 2;
            WB0[(u0 + 0) * 257 + jrow] = w.x;
            WB0[(u0 + 1) * 257 + jrow] = w.y;
            WB0[(u0 + 2) * 257 + jrow] = w.z;
            WB0[(u0 + 3) * 257 + jrow] = w.w;
        }
    }
    __syncthreads();

    // ---- pass B: logits + softmax. One warp per node (12 warps, 12 nodes).
    {
        int n = wid;
        float acc[8] = { 0.f, 0.f, 0.f, 0.f, 0.f, 0.f, 0.f, 0.f };
        const float* srow = SB + n * 128;
        #pragma unroll 2
        for (int u = 0; u < 128; u++) {
            float sv = srow[u];
            const float* lrow = WB0 + u * 257 + lane;
            #pragma unroll
            for (int kk = 0; kk < 8; kk++)
                acc[kk] = fmaf(sv, lrow[kk << 5], acc[kk]);
        }
        #pragma unroll
        for (int kk = 0; kk < 8; kk++) acc[kk] += lsb[(kk << 5) + lane];
        float m = acc[0];
        #pragma unroll
        for (int kk = 1; kk < 8; kk++) m = fmaxf(m, acc[kk]);
        #pragma unroll
        for (int off = 16; off > 0; off >>= 1)
            m = fmaxf(m, __shfl_xor_sync(0xffffffffu, m, off));
        float ssum = 0.f;
        #pragma unroll
        for (int kk = 0; kk < 8; kk++) { acc[kk] = __expf(acc[kk] - m); ssum += acc[kk]; }
        #pragma unroll
        for (int off = 16; off > 0; off >>= 1)
            ssum += __shfl_xor_sync(0xffffffffu, ssum, off);
        float inv = 1.f / ssum;
        #pragma unroll
        for (int kk = 0; kk < 8; kk++)
            PB[n * 256 + (kk << 5) + lane] = acc[kk] * inv;
    }
    __syncthreads();

    // ---- out2: su * silu(S @ lvs_w^T + b)
    stage_w129(WB0, lvw, tid);
    {
        // stage S transposed: SS2[c][n]
        int i = tid;                                  // 1536/4 = 384 float4, one per thread
        float4 t = reinterpret_cast<const float4*>(Sg + (size_t)node0 * FDIM)[i];
        float a[4] = { t.x, t.y, t.z, t.w };
        int e = i << 2;
        #pragma unroll
        for (int z = 0; z < 4; z++) {
            int ee = e + z;
            int n = ee >> 7;
            int c = ee & 127;
            SS2[c * 12 + n] = a[z];
        }
    }
    __syncthreads();
    {
        ull acc2[2] = { 0ull, 0ull };
        #pragma unroll 2
        for (int c = 0; c < 128; c++) {
            float w = WB0[c * 129 + v];
            ull w2p;
            PACKDUP(w2p, w);
            ulonglong2 t = *reinterpret_cast<const ulonglong2*>(SS2 + c * 12 + ng);
            FMA2(acc2[0], w2p, t.x, acc2[0]);
            FMA2(acc2[1], w2p, t.y, acc2[1]);
        }
        float b = lvb[v];
        float zz[4];
        {
            unsigned lo, hi;
            UNPACK2(lo, hi, acc2[0]);
            zz[0] = __uint_as_float(lo); zz[1] = __uint_as_float(hi);
            UNPACK2(lo, hi, acc2[1]);
            zz[2] = __uint_as_float(lo); zz[3] = __uint_as_float(hi);
        }
        #pragma unroll
        for (int j = 0; j < NGRP; j++) {
            int n = ng + j;
            float z   = zz[j] + b;
            float sig = 1.f / (1.f + __expf(-z));
            out2[(size_t)(node0 + n) * FDIM + v] = PB[n * 256 + v] * (z * sig);
        }
    }
    __syncthreads();   // done reading WB0 (lvw) and PB region usage for out2

    // ---- pass C: tu = sd * (Wv T) / sqrt(F) * w2 ; staged in smem, flushed coalesced
    stage_w129(WB0, Wv, tid);
    __syncthreads();
    v_pass<0, 1>(T_s, WB0, PB, w2,       TU_s, v, ng);
    __syncthreads();
    stage_w129(WB0, Wv + 16384, tid);
    __syncthreads();
    v_pass<1, 3>(T_s, WB0, PB, w2 + 128, TU_s, v, ng);
    __syncthreads();
    stage_w129(WB0, Wv + 32768, tid);
    __syncthreads();
    v_pass<4, 5>(T_s, WB0, PB, w2 + 256, TU_s, v, ng);
    __syncthreads();

    // flush TU staging: 13824 floats -> coalesced float4 stores
    {
        float4* gout = reinterpret_cast<float4*>(outT + (size_t)node0 * (FDIM * DTOT));
        const float4* s4 = reinterpret_cast<const float4*>(TU_s);
        #pragma unroll
        for (int it = 0; it < 9; it++)              // 3456 float4 / 384 threads
            gout[it * THREADS + tid] = s4[it * THREADS + tid];
    }
}

extern "C" void kernel_launch(void* const* d_in, const int* in_sizes, int n_in,
                              void* d_out, int out_size) {
    const float* Tg  = (const float*)d_in[0];
    const float* Sg  = (const float*)d_in[1];
    const float* Wq  = (const float*)d_in[2];
    const float* Wk  = (const float*)d_in[3];
    const float* Wv  = (const float*)d_in[4];
    const float* w2  = (const float*)d_in[5];
    const float* lsw = (const float*)d_in[6];
    const float* lsb = (const float*)d_in[7];
    const float* lvw = (const float*)d_in[8];
    const float* lvb = (const float*)d_in[9];

    float* out  = (float*)d_out;
    float* outT = out;                                   // tu: N*F*D floats
    float* out2 = out + (size_t)NODES * FDIM * DTOT;     // out2: N*F floats

    const int smem_bytes = 230400;
    cudaFuncSetAttribute(tp_attn_kernel,
                         cudaFuncAttributeMaxDynamicSharedMemorySize, smem_bytes);
    tp_attn_kernel<<<NODES / NB, THREADS, smem_bytes>>>(
        Tg, Sg, Wq, Wk, Wv, w2, lsw, lsb, lvw, lvb, outT, out2);
}